// round 1
// baseline (speedup 1.0000x reference)
#include <cuda_runtime.h>
#include <math.h>

#define NCOMP 32
#define NLAT  64
#define MAXC  512
#define MAXG  4000

// Scratch (static device arrays — no runtime allocation)
static __device__ float  g_delta[(size_t)MAXC * MAXG * NCOMP];   // 262 MB
static __device__ float  g_counts[MAXC * MAXG];                  // 8.2 MB
static __device__ float4 g_tab[MAXG * NCOMP];                    // {logit0, loc, inv_scale, -log(scale)-0.5log(2pi)}
static __device__ float  g_grw[MAXG * NLAT];                     // gathered rho_weight
static __device__ float  g_latT[NLAT * MAXC];                    // latent transposed [l][cell]
static __device__ float  g_logrb[MAXG];
static __device__ float  g_rb[MAXG];
static __device__ float  g_lib[MAXC];
static __device__ float  g_loglib[MAXC];
static __device__ double g_acc;

__global__ void k_init(int n) {
    int stride = gridDim.x * blockDim.x;
    for (int i = blockIdx.x * blockDim.x + threadIdx.x; i < n; i += stride)
        g_counts[i] = 0.0f;
    if (blockIdx.x == 0 && threadIdx.x == 0) g_acc = 0.0;
}

__global__ void k_scatter(const int* __restrict__ ix, int n) {
    int i = blockIdx.x * blockDim.x + threadIdx.x;
    if (i < n) atomicAdd(&g_counts[ix[i]], 1.0f);
}

__global__ void k_prep(const float* __restrict__ loc_w, const float* __restrict__ scale_w,
                       const float* __restrict__ logit_w, const float* __restrict__ rho_weight,
                       const float* __restrict__ rho_bias, const float* __restrict__ libsize,
                       const float* __restrict__ latent, const int* __restrict__ genes_oi,
                       const int* __restrict__ cells_oi, int n_genes, int n_cells) {
    int total = n_genes * NCOMP + n_genes * NLAT + n_genes + n_cells * NLAT + n_cells;
    int stride = gridDim.x * blockDim.x;
    for (int i = blockIdx.x * blockDim.x + threadIdx.x; i < total; i += stride) {
        int r = i;
        if (r < n_genes * NCOMP) {
            int g = r / NCOMP, c = r % NCOMP;
            int tg = genes_oi[g];
            float lw = loc_w[(size_t)tg * NCOMP + c];
            float sw = scale_w[(size_t)tg * NCOMP + c];
            float lg = logit_w[(size_t)tg * NCOMP + c];
            float loc = 1.0f / (1.0f + expf(-lw));
            float scale = 1e-5f + expf(sw);
            float4 t;
            t.x = lg;
            t.y = loc;
            t.z = 1.0f / scale;
            t.w = -logf(scale) - 0.91893853320467274f; // -log(scale) - 0.5*log(2pi)
            g_tab[r] = t;
            continue;
        }
        r -= n_genes * NCOMP;
        if (r < n_genes * NLAT) {
            int g = r / NLAT, l = r % NLAT;
            g_grw[r] = rho_weight[(size_t)genes_oi[g] * NLAT + l];
            continue;
        }
        r -= n_genes * NLAT;
        if (r < n_genes) {
            float rb = rho_bias[genes_oi[r]];
            g_rb[r] = rb;
            g_logrb[r] = logf(rb);
            continue;
        }
        r -= n_genes;
        if (r < n_cells * NLAT) {
            int l = r / n_cells, cell = r % n_cells;
            g_latT[r] = latent[(size_t)cell * NLAT + l]; // g_latT[l*n_cells + cell]
            continue;
        }
        r -= n_cells * NLAT;
        {
            float lb = libsize[cells_oi[r]];
            g_lib[r] = lb;
            g_loglib[r] = logf(lb);
        }
    }
}

// delta[n,g,c] = sum_l latent[n,l] * logit_weight[genes_oi[g], l, c]
// Block: one gene x 64-cell chunk. 256 threads: thread = (cell 0..63, cgroup 0..3), 8 comps each.
__global__ void k_gemm(const float* __restrict__ logit_weight, const int* __restrict__ genes_oi,
                       int n_cells, int n_genes) {
    __shared__ float lw_s[NLAT][NCOMP];     // [l][c]  8 KB
    __shared__ float lat_s[NLAT][64];       // [l][cell] 16 KB

    int g = blockIdx.x;
    int chunk = blockIdx.y;
    int tid = threadIdx.x;

    int tg = genes_oi[g];
    const float* src = logit_weight + (size_t)tg * (NLAT * NCOMP);
    for (int i = tid; i < NLAT * NCOMP; i += 256)
        ((float*)lw_s)[i] = src[i];                       // same [l][c] layout
    int cbase = chunk * 64;
    for (int i = tid; i < NLAT * 64; i += 256) {
        int l = i >> 6, c2 = i & 63;
        lat_s[l][c2] = g_latT[l * n_cells + cbase + c2];
    }
    __syncthreads();

    int cell = tid >> 2;
    int cg = tid & 3;
    float acc[8] = {0, 0, 0, 0, 0, 0, 0, 0};
#pragma unroll
    for (int l = 0; l < NLAT; l++) {
        float a = lat_s[l][cell];
        float4 b0 = *(const float4*)&lw_s[l][cg * 8];
        float4 b1 = *(const float4*)&lw_s[l][cg * 8 + 4];
        acc[0] = fmaf(a, b0.x, acc[0]);
        acc[1] = fmaf(a, b0.y, acc[1]);
        acc[2] = fmaf(a, b0.z, acc[2]);
        acc[3] = fmaf(a, b0.w, acc[3]);
        acc[4] = fmaf(a, b1.x, acc[4]);
        acc[5] = fmaf(a, b1.y, acc[5]);
        acc[6] = fmaf(a, b1.z, acc[6]);
        acc[7] = fmaf(a, b1.w, acc[7]);
    }
    size_t base = ((size_t)(cbase + cell) * n_genes + g) * NCOMP + cg * 8;
    *(float4*)&g_delta[base]     = make_float4(acc[0], acc[1], acc[2], acc[3]);
    *(float4*)&g_delta[base + 4] = make_float4(acc[4], acc[5], acc[6], acc[7]);
}

// Poisson fragment-count likelihood over all (cell, gene) pairs.
// Block: 8 genes x 256 cells.
__global__ void k_poisson(int n_cells, int n_genes) {
    __shared__ float rw_s[8][NLAT];
    __shared__ float red[8];

    int gbase = blockIdx.x * 8;
    int cell = blockIdx.y * 256 + threadIdx.x;
    int tid = threadIdx.x;

    for (int i = tid; i < 8 * NLAT; i += 256) {
        int j = i / NLAT, l = i % NLAT;
        int g = gbase + j;
        rw_s[j][l] = (g < n_genes) ? g_grw[g * NLAT + l] : 0.0f;
    }
    __syncthreads();

    float lsum = 0.0f;
    if (cell < n_cells) {
        float acc[8] = {0, 0, 0, 0, 0, 0, 0, 0};
#pragma unroll 16
        for (int l = 0; l < NLAT; l++) {
            float lat = g_latT[l * n_cells + cell];
#pragma unroll
            for (int j = 0; j < 8; j++)
                acc[j] = fmaf(lat, rw_s[j][l], acc[j]);
        }
        float lib = g_lib[cell], ll = g_loglib[cell];
#pragma unroll
        for (int j = 0; j < 8; j++) {
            int g = gbase + j;
            if (g >= n_genes) continue;
            float rho = acc[j];
            float fe = g_rb[g] * __expf(rho) * lib;
            float cnt = g_counts[(size_t)cell * n_genes + g];
            float t = cnt * (g_logrb[g] + rho + ll) - fe;
            if (cnt > 1.5f) t -= lgammaf(cnt + 1.0f);
            lsum += t;
        }
    }
    // block reduce
    for (int s = 16; s > 0; s >>= 1) lsum += __shfl_xor_sync(0xffffffffu, lsum, s);
    int wid = tid >> 5;
    if ((tid & 31) == 0) red[wid] = lsum;
    __syncthreads();
    if (tid == 0) {
        float s = 0.0f;
        for (int i = 0; i < 8; i++) s += red[i];
        atomicAdd(&g_acc, (double)s);
    }
}

// Mixture likelihood: one warp per cut, lane = component.
__global__ void k_mix(const int* __restrict__ cpx, const int* __restrict__ cgx,
                      const float* __restrict__ coord, int n_cuts) {
    __shared__ float red[8];
    int lane = threadIdx.x & 31;
    int wid = threadIdx.x >> 5;
    int gw = blockIdx.x * 8 + wid;
    int nwarps = gridDim.x * 8;

    float local = 0.0f;
    for (int k = gw; k < n_cuts; k += nwarps) {
        int pair = cpx[k];
        int g = cgx[k];
        float x = coord[k];
        float4 t = g_tab[g * NCOMP + lane];
        float d = g_delta[(size_t)pair * NCOMP + lane];
        float logit = t.x + d;
        float z = (x - t.y) * t.z;
        float a = fmaf(-0.5f * z, z, logit + t.w);
        float m1 = a, m2 = logit;
#pragma unroll
        for (int s = 16; s > 0; s >>= 1) {
            m1 = fmaxf(m1, __shfl_xor_sync(0xffffffffu, m1, s));
            m2 = fmaxf(m2, __shfl_xor_sync(0xffffffffu, m2, s));
        }
        float e1 = __expf(a - m1);
        float e2 = __expf(logit - m2);
#pragma unroll
        for (int s = 16; s > 0; s >>= 1) {
            e1 += __shfl_xor_sync(0xffffffffu, e1, s);
            e2 += __shfl_xor_sync(0xffffffffu, e2, s);
        }
        local += (m1 + __logf(e1)) - (m2 + __logf(e2));
    }
    if (lane == 0) red[wid] = local;
    __syncthreads();
    if (threadIdx.x == 0) {
        float s = 0.0f;
        for (int i = 0; i < 8; i++) s += red[i];
        atomicAdd(&g_acc, (double)s);
    }
}

__global__ void k_final(float* out) {
    out[0] = (float)(-g_acc);
}

extern "C" void kernel_launch(void* const* d_in, const int* in_sizes, int n_in,
                              void* d_out, int out_size) {
    const int*   frag_ix      = (const int*)d_in[0];
    const float* coord        = (const float*)d_in[1];
    const float* latent       = (const float*)d_in[2];
    const int*   genes_oi     = (const int*)d_in[3];
    const int*   cells_oi     = (const int*)d_in[4];
    const int*   cpx          = (const int*)d_in[5];
    const int*   cgx          = (const int*)d_in[6];
    // d_in[7], d_in[8]: n_cells, n_genes scalars (use in_sizes instead)
    const float* loc_w        = (const float*)d_in[9];
    const float* scale_w      = (const float*)d_in[10];
    const float* logit_w      = (const float*)d_in[11];
    const float* logit_weight = (const float*)d_in[12];
    const float* rho_weight   = (const float*)d_in[13];
    const float* rho_bias     = (const float*)d_in[14];
    const float* libsize      = (const float*)d_in[15];

    int n_frags = in_sizes[0];
    int n_cuts  = in_sizes[1];
    int n_genes = in_sizes[3];
    int n_cells = in_sizes[4];

    k_init<<<512, 256>>>(n_cells * n_genes);
    k_scatter<<<(n_frags + 255) / 256, 256>>>(frag_ix, n_frags);
    k_prep<<<1024, 256>>>(loc_w, scale_w, logit_w, rho_weight, rho_bias, libsize,
                          latent, genes_oi, cells_oi, n_genes, n_cells);
    dim3 gg(n_genes, (n_cells + 63) / 64);
    k_gemm<<<gg, 256>>>(logit_weight, genes_oi, n_cells, n_genes);
    dim3 gp((n_genes + 7) / 8, (n_cells + 255) / 256);
    k_poisson<<<gp, 256>>>(n_cells, n_genes);
    k_mix<<<2048, 256>>>(cpx, cgx, coord, n_cuts);
    k_final<<<1, 1>>>((float*)d_out);
}

// round 6
// speedup vs baseline: 3.5332x; 3.5332x over previous
#include <cuda_runtime.h>
#include <cuda_bf16.h>
#include <math.h>

#define NCOMP 32
#define NLAT  64
#define MAXC  512
#define MAXG  4000

// Scratch (static device arrays — no runtime allocation)
static __device__ float  g_delta[(size_t)MAXC * MAXG * NCOMP];   // 262 MB
static __device__ float  g_counts[MAXC * MAXG];                  // 8.2 MB
static __device__ float4 g_tab[MAXG * NCOMP];                    // {logit0, loc, inv_scale, -log(scale)-0.5log(2pi)}
static __device__ float  g_grw[MAXG * NLAT];                     // gathered rho_weight
static __device__ float  g_latT[NLAT * MAXC];                    // latent transposed [l][cell]
static __device__ __nv_bfloat16 g_latb[MAXC * NLAT];             // latent bf16 [cell][l]
static __device__ __nv_bfloat16 g_lwb[(size_t)MAXG * NCOMP * NLAT]; // weights bf16 [g][c][k] (K-major)
static __device__ float  g_logrb[MAXG];
static __device__ float  g_rb[MAXG];
static __device__ float  g_lib[MAXC];
static __device__ float  g_loglib[MAXC];
static __device__ double g_acc;

// ---------------- simple kernels ----------------
__global__ void k_init(int n) {
    int stride = gridDim.x * blockDim.x;
    for (int i = blockIdx.x * blockDim.x + threadIdx.x; i < n; i += stride)
        g_counts[i] = 0.0f;
    if (blockIdx.x == 0 && threadIdx.x == 0) g_acc = 0.0;
}

__global__ void k_scatter(const int* __restrict__ ix, int n) {
    int i = blockIdx.x * blockDim.x + threadIdx.x;
    if (i < n) atomicAdd(&g_counts[ix[i]], 1.0f);
}

__global__ void k_prep(const float* __restrict__ loc_w, const float* __restrict__ scale_w,
                       const float* __restrict__ logit_w, const float* __restrict__ rho_weight,
                       const float* __restrict__ rho_bias, const float* __restrict__ libsize,
                       const float* __restrict__ latent, const int* __restrict__ genes_oi,
                       const int* __restrict__ cells_oi, int n_genes, int n_cells) {
    int total = n_genes * NCOMP + n_genes * NLAT + n_genes + n_cells * NLAT + n_cells;
    int stride = gridDim.x * blockDim.x;
    for (int i = blockIdx.x * blockDim.x + threadIdx.x; i < total; i += stride) {
        int r = i;
        if (r < n_genes * NCOMP) {
            int g = r / NCOMP, c = r % NCOMP;
            int tg = genes_oi[g];
            float lw = loc_w[(size_t)tg * NCOMP + c];
            float sw = scale_w[(size_t)tg * NCOMP + c];
            float lg = logit_w[(size_t)tg * NCOMP + c];
            float loc = 1.0f / (1.0f + expf(-lw));
            float scale = 1e-5f + expf(sw);
            float4 t;
            t.x = lg;
            t.y = loc;
            t.z = 1.0f / scale;
            t.w = -logf(scale) - 0.91893853320467274f;
            g_tab[r] = t;
            continue;
        }
        r -= n_genes * NCOMP;
        if (r < n_genes * NLAT) {
            int g = r / NLAT, l = r % NLAT;
            g_grw[r] = rho_weight[(size_t)genes_oi[g] * NLAT + l];
            continue;
        }
        r -= n_genes * NLAT;
        if (r < n_genes) {
            float rb = rho_bias[genes_oi[r]];
            g_rb[r] = rb;
            g_logrb[r] = logf(rb);
            continue;
        }
        r -= n_genes;
        if (r < n_cells * NLAT) {
            int l = r / n_cells, cell = r % n_cells;
            float v = latent[(size_t)cell * NLAT + l];
            g_latT[r] = v;                                   // [l][cell]
            g_latb[(size_t)cell * NLAT + l] = __float2bfloat16(v);
            continue;
        }
        r -= n_cells * NLAT;
        {
            float lb = libsize[cells_oi[r]];
            g_lib[r] = lb;
            g_loglib[r] = logf(lb);
        }
    }
}

// Transpose+convert gathered weights: g_lwb[g][c][k] = bf16(logit_weight[tg][k][c])
__global__ void k_tr(const float* __restrict__ logit_weight, const int* __restrict__ genes_oi) {
    __shared__ float ts[NLAT][NCOMP + 1];
    int g = blockIdx.x;
    int tg = genes_oi[g];
    const float* src = logit_weight + (size_t)tg * (NLAT * NCOMP);
    int tid = threadIdx.x;
    for (int i = tid; i < NLAT * NCOMP; i += 256)
        ts[i >> 5][i & 31] = src[i];
    __syncthreads();
    __nv_bfloat16* dst = g_lwb + (size_t)g * (NCOMP * NLAT);
    for (int i = tid; i < NCOMP * NLAT; i += 256) {
        int c = i >> 6, k = i & 63;
        dst[i] = __float2bfloat16(ts[k][c]);
    }
}

// ---------------- mma.sync bf16 GEMM: delta = latent @ W ----------------
// D[512, n_genes*32] = A[512, 64] @ B[64, n_genes*32]; B column (32g+c) = g_lwb[g][c][:].
// CTA: 128 cells (M) x 128 cols (4 genes, N), K=64 fully resident.
// 8 warps: warp grid 4(M) x 2(N) -> warp tile 32x64 = 2x8 m16n8k16 tiles x 4 k-chunks.
#define ASTRIDE 72  // padded row stride in bf16 elems (144B) -> conflict-free frag loads

__device__ __forceinline__ void mma_bf16(float* c, const unsigned* a, const unsigned* b) {
    asm volatile(
        "mma.sync.aligned.m16n8k16.row.col.f32.bf16.bf16.f32 "
        "{%0,%1,%2,%3}, {%4,%5,%6,%7}, {%8,%9}, {%0,%1,%2,%3};"
        : "+f"(c[0]), "+f"(c[1]), "+f"(c[2]), "+f"(c[3])
        : "r"(a[0]), "r"(a[1]), "r"(a[2]), "r"(a[3]), "r"(b[0]), "r"(b[1]));
}

__global__ void __launch_bounds__(256) k_gemm_mma(int n_cells, int n_genes) {
    __shared__ __nv_bfloat16 As[128 * ASTRIDE];
    __shared__ __nv_bfloat16 Bs[128 * ASTRIDE];

    int tid = threadIdx.x;
    int gbase = blockIdx.x * 4;     // 4 genes -> 128 output cols
    int cbase = blockIdx.y * 128;   // 128 cells

    // Fill smem: 1024 16B-chunks per tile (128 rows x 8 chunks), padded rows.
    const uint4* asrc = (const uint4*)(g_latb + (size_t)cbase * NLAT);
    const uint4* bsrc = (const uint4*)(g_lwb + (size_t)gbase * (NCOMP * NLAT));
#pragma unroll
    for (int i = 0; i < 4; i++) {
        int cid = i * 256 + tid;
        int row = cid >> 3, ch = cid & 7;
        *(uint4*)(As + row * ASTRIDE + ch * 8) = asrc[cid];
        *(uint4*)(Bs + row * ASTRIDE + ch * 8) = bsrc[cid];
    }
    __syncthreads();

    int wid = tid >> 5, lane = tid & 31;
    int wm = (wid & 3) * 32;    // warp M offset within CTA tile
    int wn = (wid >> 2) * 64;   // warp N offset
    int g = lane >> 2, t = lane & 3;

    float acc[2][8][4];
#pragma unroll
    for (int mt = 0; mt < 2; mt++)
#pragma unroll
        for (int nt = 0; nt < 8; nt++)
#pragma unroll
            for (int j = 0; j < 4; j++) acc[mt][nt][j] = 0.0f;

#pragma unroll
    for (int kc = 0; kc < 4; kc++) {
        int k0 = kc * 16;
        unsigned a[2][4];
#pragma unroll
        for (int mt = 0; mt < 2; mt++) {
            int r0 = wm + mt * 16 + g;
            a[mt][0] = *(const unsigned*)(As + (r0)     * ASTRIDE + k0 + 2 * t);
            a[mt][1] = *(const unsigned*)(As + (r0 + 8) * ASTRIDE + k0 + 2 * t);
            a[mt][2] = *(const unsigned*)(As + (r0)     * ASTRIDE + k0 + 2 * t + 8);
            a[mt][3] = *(const unsigned*)(As + (r0 + 8) * ASTRIDE + k0 + 2 * t + 8);
        }
        unsigned b[8][2];
#pragma unroll
        for (int nt = 0; nt < 8; nt++) {
            int n0 = wn + nt * 8 + g;
            b[nt][0] = *(const unsigned*)(Bs + n0 * ASTRIDE + k0 + 2 * t);
            b[nt][1] = *(const unsigned*)(Bs + n0 * ASTRIDE + k0 + 2 * t + 8);
        }
#pragma unroll
        for (int mt = 0; mt < 2; mt++)
#pragma unroll
            for (int nt = 0; nt < 8; nt++)
                mma_bf16(acc[mt][nt], a[mt], b[nt]);
    }

    // Epilogue: c0,c1 -> (row g, cols 2t,2t+1); c2,c3 -> (row g+8).
    size_t rowstride = (size_t)n_genes * NCOMP;
    float* dbase = g_delta + (size_t)gbase * NCOMP;
#pragma unroll
    for (int mt = 0; mt < 2; mt++) {
        int r0 = cbase + wm + mt * 16 + g;
#pragma unroll
        for (int nt = 0; nt < 8; nt++) {
            int col = wn + nt * 8 + 2 * t;
            *(float2*)(dbase + (size_t)r0 * rowstride + col) =
                make_float2(acc[mt][nt][0], acc[mt][nt][1]);
            *(float2*)(dbase + (size_t)(r0 + 8) * rowstride + col) =
                make_float2(acc[mt][nt][2], acc[mt][nt][3]);
        }
    }
}

// ---------------- Poisson fragment-count likelihood ----------------
__global__ void k_poisson(int n_cells, int n_genes) {
    __shared__ float rw_s[8][NLAT];
    __shared__ float red[8];

    int gbase = blockIdx.x * 8;
    int cell = blockIdx.y * 256 + threadIdx.x;
    int tid = threadIdx.x;

    for (int i = tid; i < 8 * NLAT; i += 256) {
        int j = i / NLAT, l = i % NLAT;
        int g = gbase + j;
        rw_s[j][l] = (g < n_genes) ? g_grw[g * NLAT + l] : 0.0f;
    }
    __syncthreads();

    float lsum = 0.0f;
    if (cell < n_cells) {
        float acc[8] = {0, 0, 0, 0, 0, 0, 0, 0};
#pragma unroll 16
        for (int l = 0; l < NLAT; l++) {
            float lat = g_latT[l * n_cells + cell];
#pragma unroll
            for (int j = 0; j < 8; j++)
                acc[j] = fmaf(lat, rw_s[j][l], acc[j]);
        }
        float lib = g_lib[cell], ll = g_loglib[cell];
#pragma unroll
        for (int j = 0; j < 8; j++) {
            int g = gbase + j;
            if (g >= n_genes) continue;
            float rho = acc[j];
            float fe = g_rb[g] * __expf(rho) * lib;
            float cnt = g_counts[(size_t)cell * n_genes + g];
            float t = cnt * (g_logrb[g] + rho + ll) - fe;
            if (cnt > 1.5f) t -= lgammaf(cnt + 1.0f);
            lsum += t;
        }
    }
    for (int s = 16; s > 0; s >>= 1) lsum += __shfl_xor_sync(0xffffffffu, lsum, s);
    int wid = tid >> 5;
    if ((tid & 31) == 0) red[wid] = lsum;
    __syncthreads();
    if (tid == 0) {
        float s = 0.0f;
        for (int i = 0; i < 8; i++) s += red[i];
        atomicAdd(&g_acc, (double)s);
    }
}

// ---------------- Mixture likelihood: one warp per cut ----------------
__global__ void k_mix(const int* __restrict__ cpx, const int* __restrict__ cgx,
                      const float* __restrict__ coord, int n_cuts) {
    __shared__ float red[8];
    int lane = threadIdx.x & 31;
    int wid = threadIdx.x >> 5;
    int gw = blockIdx.x * 8 + wid;
    int nwarps = gridDim.x * 8;

    float local = 0.0f;
    for (int k = gw; k < n_cuts; k += nwarps) {
        int pair = cpx[k];
        int g = cgx[k];
        float x = coord[k];
        float4 t = g_tab[g * NCOMP + lane];
        float d = g_delta[(size_t)pair * NCOMP + lane];
        float logit = t.x + d;
        float z = (x - t.y) * t.z;
        float a = fmaf(-0.5f * z, z, logit + t.w);
        float m1 = a, m2 = logit;
#pragma unroll
        for (int s = 16; s > 0; s >>= 1) {
            m1 = fmaxf(m1, __shfl_xor_sync(0xffffffffu, m1, s));
            m2 = fmaxf(m2, __shfl_xor_sync(0xffffffffu, m2, s));
        }
        float e1 = __expf(a - m1);
        float e2 = __expf(logit - m2);
#pragma unroll
        for (int s = 16; s > 0; s >>= 1) {
            e1 += __shfl_xor_sync(0xffffffffu, e1, s);
            e2 += __shfl_xor_sync(0xffffffffu, e2, s);
        }
        local += (m1 + __logf(e1)) - (m2 + __logf(e2));
    }
    if (lane == 0) red[wid] = local;
    __syncthreads();
    if (threadIdx.x == 0) {
        float s = 0.0f;
        for (int i = 0; i < 8; i++) s += red[i];
        atomicAdd(&g_acc, (double)s);
    }
}

__global__ void k_final(float* out) {
    out[0] = (float)(-g_acc);
}

extern "C" void kernel_launch(void* const* d_in, const int* in_sizes, int n_in,
                              void* d_out, int out_size) {
    const int*   frag_ix      = (const int*)d_in[0];
    const float* coord        = (const float*)d_in[1];
    const float* latent       = (const float*)d_in[2];
    const int*   genes_oi     = (const int*)d_in[3];
    const int*   cells_oi     = (const int*)d_in[4];
    const int*   cpx          = (const int*)d_in[5];
    const int*   cgx          = (const int*)d_in[6];
    const float* loc_w        = (const float*)d_in[9];
    const float* scale_w      = (const float*)d_in[10];
    const float* logit_w      = (const float*)d_in[11];
    const float* logit_weight = (const float*)d_in[12];
    const float* rho_weight   = (const float*)d_in[13];
    const float* rho_bias     = (const float*)d_in[14];
    const float* libsize      = (const float*)d_in[15];

    int n_frags = in_sizes[0];
    int n_cuts  = in_sizes[1];
    int n_genes = in_sizes[3];
    int n_cells = in_sizes[4];

    k_init<<<512, 256>>>(n_cells * n_genes);
    k_scatter<<<(n_frags + 255) / 256, 256>>>(frag_ix, n_frags);
    k_prep<<<1024, 256>>>(loc_w, scale_w, logit_w, rho_weight, rho_bias, libsize,
                          latent, genes_oi, cells_oi, n_genes, n_cells);
    k_tr<<<n_genes, 256>>>(logit_weight, genes_oi);
    dim3 gg(n_genes / 4, n_cells / 128);
    k_gemm_mma<<<gg, 256>>>(n_cells, n_genes);
    dim3 gp((n_genes + 7) / 8, (n_cells + 255) / 256);
    k_poisson<<<gp, 256>>>(n_cells, n_genes);
    k_mix<<<2048, 256>>>(cpx, cgx, coord, n_cuts);
    k_final<<<1, 1>>>((float*)d_out);
}